// round 1
// baseline (speedup 1.0000x reference)
#include <cuda_runtime.h>

#define C_DIM   768
#define QKV_DIM 3072
#define BATCH   4
#define SEQ     1024
#define HEADS   12
#define HD      64
#define M_ROWS  (BATCH*SEQ)   // 4096

// -------- scratch (allocation-free: device globals) --------
__device__ float g_qkv_x[BATCH*SEQ*QKV_DIM];   // 50.3 MB
__device__ float g_qkv_y[BATCH*SEQ*QKV_DIM];   // 50.3 MB
__device__ float g_att_x[BATCH*SEQ*C_DIM];     // 12.6 MB
__device__ float g_att_y[BATCH*SEQ*C_DIM];     // 12.6 MB

// ============================================================
// SGEMM: C[m,n] = sum_k A[m,k] * B[n,k] (+ bias[n])
// A: [M,K] row-major, B: [N,K] row-major, C: [M,N] row-major.
// BM=BN=128, BK=16, 256 threads, 8x8 microtile.
// M,N multiples of 128; K multiple of 16 (true for all our calls).
// ============================================================
__global__ __launch_bounds__(256) void sgemm_nt(
    const float* __restrict__ A, const float* __restrict__ B,
    const float* __restrict__ bias, float* __restrict__ C,
    int M, int N, int K)
{
    __shared__ float As[16][132];
    __shared__ float Bs[16][132];

    const int tid = threadIdx.x;
    const int tx  = tid & 15;
    const int ty  = tid >> 4;
    const int m0  = blockIdx.y * 128;
    const int n0  = blockIdx.x * 128;

    float acc[8][8];
#pragma unroll
    for (int i = 0; i < 8; i++)
#pragma unroll
        for (int j = 0; j < 8; j++) acc[i][j] = 0.f;

    for (int kb = 0; kb < K; kb += 16) {
#pragma unroll
        for (int u = 0; u < 2; u++) {
            int f   = tid + u * 256;      // 0..511
            int row = f >> 2;             // 0..127
            int kq  = (f & 3) << 2;       // 0,4,8,12
            float4 av = *(const float4*)(A + (size_t)(m0 + row) * K + kb + kq);
            As[kq+0][row] = av.x; As[kq+1][row] = av.y;
            As[kq+2][row] = av.z; As[kq+3][row] = av.w;
            float4 bv = *(const float4*)(B + (size_t)(n0 + row) * K + kb + kq);
            Bs[kq+0][row] = bv.x; Bs[kq+1][row] = bv.y;
            Bs[kq+2][row] = bv.z; Bs[kq+3][row] = bv.w;
        }
        __syncthreads();

#pragma unroll
        for (int kk = 0; kk < 16; kk++) {
            float a[8], b[8];
            *(float4*)&a[0] = *(const float4*)&As[kk][ty * 8];
            *(float4*)&a[4] = *(const float4*)&As[kk][ty * 8 + 4];
            *(float4*)&b[0] = *(const float4*)&Bs[kk][tx * 8];
            *(float4*)&b[4] = *(const float4*)&Bs[kk][tx * 8 + 4];
#pragma unroll
            for (int i = 0; i < 8; i++)
#pragma unroll
                for (int j = 0; j < 8; j++)
                    acc[i][j] += a[i] * b[j];
        }
        __syncthreads();
    }

    float bb[8];
#pragma unroll
    for (int j = 0; j < 8; j++)
        bb[j] = bias ? bias[n0 + tx * 8 + j] : 0.f;

#pragma unroll
    for (int i = 0; i < 8; i++) {
        float* crow = C + (size_t)(m0 + ty * 8 + i) * N + n0 + tx * 8;
#pragma unroll
        for (int j = 0; j < 8; j += 4) {
            float4 o;
            o.x = acc[i][j+0] + bb[j+0];
            o.y = acc[i][j+1] + bb[j+1];
            o.z = acc[i][j+2] + bb[j+2];
            o.w = acc[i][j+3] + bb[j+3];
            *(float4*)(crow + j) = o;
        }
    }
}

// ============================================================
// Fused dual-softmax flash attention.
// Each block: one (batch b, head h, branch, 64-row q-tile).
//   branch 0 (x): Q1=qx (+), Q2=qyo (-), K=kx, V=vx -> g_att_x
//   branch 1 (y): Q1=qy (+), Q2=qxo (-), K=ky, V=vx -> g_att_y
// Output = softmax(+S1)V + softmax(-S2)V   (already summed for proj).
// 256 threads: tx (0..15) -> 4 cols, ty (0..15) -> 4 rows.
// ============================================================
#define SROW 68                       // padded smem row stride (floats)
#define ATT_SMEM (6 * 64 * SROW * 4)  // 104448 bytes

__device__ __forceinline__ void softmax_update(
    const float s[4][4], float sgn,
    float m[4], float l[4], float O[4][4],
    float* __restrict__ P, int tx, int ty)
{
#pragma unroll
    for (int r = 0; r < 4; r++) {
        float sv[4];
#pragma unroll
        for (int c = 0; c < 4; c++) sv[c] = s[r][c] * sgn;
        float mx = fmaxf(fmaxf(sv[0], sv[1]), fmaxf(sv[2], sv[3]));
#pragma unroll
        for (int off = 8; off >= 1; off >>= 1)
            mx = fmaxf(mx, __shfl_xor_sync(0xffffffffu, mx, off));
        float mnew = fmaxf(m[r], mx);
        float corr = __expf(m[r] - mnew);
        float p[4], sum = 0.f;
#pragma unroll
        for (int c = 0; c < 4; c++) { p[c] = __expf(sv[c] - mnew); sum += p[c]; }
#pragma unroll
        for (int off = 8; off >= 1; off >>= 1)
            sum += __shfl_xor_sync(0xffffffffu, sum, off);
        l[r] = l[r] * corr + sum;
        m[r] = mnew;
#pragma unroll
        for (int c = 0; c < 4; c++) O[r][c] *= corr;
        // P stored [j][i] for vectorized PV reads
#pragma unroll
        for (int c = 0; c < 4; c++)
            P[(tx * 4 + c) * SROW + ty * 4 + r] = p[c];
    }
}

__global__ __launch_bounds__(256, 2) void attention_kernel()
{
    extern __shared__ float sm[];
    float* Q1t = sm;                  // [d][i]
    float* Q2t = sm + 1 * 64 * SROW;  // [d][i]
    float* Kt  = sm + 2 * 64 * SROW;  // [d][j]
    float* Vs  = sm + 3 * 64 * SROW;  // [j][d]
    float* P1  = sm + 4 * 64 * SROW;  // [j][i]
    float* P2  = sm + 5 * 64 * SROW;  // [j][i]

    const int b    = blockIdx.z;
    const int h    = blockIdx.y >> 1;
    const int pair = blockIdx.y & 1;
    const int q0   = blockIdx.x * 64;
    const int tid  = threadIdx.x;
    const int tx   = tid & 15;
    const int ty   = tid >> 4;

    const float* bx = g_qkv_x + (size_t)b * SEQ * QKV_DIM;
    const float* by = g_qkv_y + (size_t)b * SEQ * QKV_DIM;
    const int hoff  = h * HD;

    const float *Q1src, *Q2src, *Ksrc;
    float* outp;
    if (pair == 0) { Q1src = bx + C_DIM; Q2src = by;  Ksrc = bx + 2 * C_DIM; outp = g_att_x; }
    else           { Q1src = by + C_DIM; Q2src = bx;  Ksrc = by + 2 * C_DIM; outp = g_att_y; }
    const float* Vsrc = bx + 3 * C_DIM;   // vy = vx in the reference

    // ---- load Q tiles, transposed to [d][i] ----
    for (int t = tid; t < 64 * 16; t += 256) {
        int r  = t >> 4;
        int d4 = (t & 15) << 2;
        float4 v1 = *(const float4*)(Q1src + (size_t)(q0 + r) * QKV_DIM + hoff + d4);
        float4 v2 = *(const float4*)(Q2src + (size_t)(q0 + r) * QKV_DIM + hoff + d4);
        Q1t[(d4+0)*SROW + r] = v1.x; Q1t[(d4+1)*SROW + r] = v1.y;
        Q1t[(d4+2)*SROW + r] = v1.z; Q1t[(d4+3)*SROW + r] = v1.w;
        Q2t[(d4+0)*SROW + r] = v2.x; Q2t[(d4+1)*SROW + r] = v2.y;
        Q2t[(d4+2)*SROW + r] = v2.z; Q2t[(d4+3)*SROW + r] = v2.w;
    }

    float O1[4][4], O2[4][4];
    float m1[4], l1[4], m2[4], l2[4];
#pragma unroll
    for (int r = 0; r < 4; r++) {
        m1[r] = -1e30f; m2[r] = -1e30f; l1[r] = 0.f; l2[r] = 0.f;
#pragma unroll
        for (int c = 0; c < 4; c++) { O1[r][c] = 0.f; O2[r][c] = 0.f; }
    }

    const float SC = 0.125f;   // hd^-0.5

    for (int kt = 0; kt < 16; kt++) {
        const int j0 = kt * 64;
        __syncthreads();   // previous PV readers done before K/V/P reuse
        for (int t = tid; t < 64 * 16; t += 256) {
            int r  = t >> 4;
            int d4 = (t & 15) << 2;
            float4 kv = *(const float4*)(Ksrc + (size_t)(j0 + r) * QKV_DIM + hoff + d4);
            Kt[(d4+0)*SROW + r] = kv.x; Kt[(d4+1)*SROW + r] = kv.y;
            Kt[(d4+2)*SROW + r] = kv.z; Kt[(d4+3)*SROW + r] = kv.w;
            float4 vv = *(const float4*)(Vsrc + (size_t)(j0 + r) * QKV_DIM + hoff + d4);
            *(float4*)&Vs[r * SROW + d4] = vv;
        }
        __syncthreads();

        // ---- S = Q K^T for both Q variants ----
        float s1[4][4], s2[4][4];
#pragma unroll
        for (int r = 0; r < 4; r++)
#pragma unroll
            for (int c = 0; c < 4; c++) { s1[r][c] = 0.f; s2[r][c] = 0.f; }

#pragma unroll 8
        for (int d = 0; d < 64; d++) {
            float4 q1 = *(const float4*)&Q1t[d * SROW + ty * 4];
            float4 q2 = *(const float4*)&Q2t[d * SROW + ty * 4];
            float4 kk = *(const float4*)&Kt [d * SROW + tx * 4];
            float qa1[4] = {q1.x, q1.y, q1.z, q1.w};
            float qa2[4] = {q2.x, q2.y, q2.z, q2.w};
            float ka [4] = {kk.x, kk.y, kk.z, kk.w};
#pragma unroll
            for (int r = 0; r < 4; r++)
#pragma unroll
                for (int c = 0; c < 4; c++) {
                    s1[r][c] += qa1[r] * ka[c];
                    s2[r][c] += qa2[r] * ka[c];
                }
        }

        softmax_update(s1,  SC, m1, l1, O1, P1, tx, ty);
        softmax_update(s2, -SC, m2, l2, O2, P2, tx, ty);
        __syncthreads();

        // ---- O += P V ----
#pragma unroll 8
        for (int j = 0; j < 64; j++) {
            float4 vv = *(const float4*)&Vs[j * SROW + tx * 4];
            float4 pa = *(const float4*)&P1[j * SROW + ty * 4];
            float4 pb = *(const float4*)&P2[j * SROW + ty * 4];
            float va[4]  = {vv.x, vv.y, vv.z, vv.w};
            float pa1[4] = {pa.x, pa.y, pa.z, pa.w};
            float pa2[4] = {pb.x, pb.y, pb.z, pb.w};
#pragma unroll
            for (int r = 0; r < 4; r++)
#pragma unroll
                for (int c = 0; c < 4; c++) {
                    O1[r][c] += pa1[r] * va[c];
                    O2[r][c] += pa2[r] * va[c];
                }
        }
    }

    // ---- epilogue: out = O1/l1 + O2/l2, layout [B,N,C] ----
#pragma unroll
    for (int r = 0; r < 4; r++) {
        float inv1 = 1.f / l1[r];
        float inv2 = 1.f / l2[r];
        float4 o;
        o.x = O1[r][0] * inv1 + O2[r][0] * inv2;
        o.y = O1[r][1] * inv1 + O2[r][1] * inv2;
        o.z = O1[r][2] * inv1 + O2[r][2] * inv2;
        o.w = O1[r][3] * inv1 + O2[r][3] * inv2;
        *(float4*)(outp + (size_t)b * SEQ * C_DIM
                        + (size_t)(q0 + ty * 4 + r) * C_DIM
                        + hoff + tx * 4) = o;
    }
}

// ============================================================
extern "C" void kernel_launch(void* const* d_in, const int* in_sizes, int n_in,
                              void* d_out, int out_size)
{
    const float* x      = (const float*)d_in[0];
    const float* y      = (const float*)d_in[1];
    const float* w_qkv  = (const float*)d_in[2];
    const float* w_proj = (const float*)d_in[3];
    const float* b_proj = (const float*)d_in[4];
    float* out = (float*)d_out;

    float *qx, *qy, *ax, *ay;
    cudaGetSymbolAddress((void**)&qx, g_qkv_x);
    cudaGetSymbolAddress((void**)&qy, g_qkv_y);
    cudaGetSymbolAddress((void**)&ax, g_att_x);
    cudaGetSymbolAddress((void**)&ay, g_att_y);

    cudaFuncSetAttribute(attention_kernel,
                         cudaFuncAttributeMaxDynamicSharedMemorySize, ATT_SMEM);

    // 1) QKV projections: [4096,768] @ [3072,768]^T
    dim3 g1(QKV_DIM / 128, M_ROWS / 128);
    sgemm_nt<<<g1, 256>>>(x, w_qkv, nullptr, qx, M_ROWS, QKV_DIM, C_DIM);
    sgemm_nt<<<g1, 256>>>(y, w_qkv, nullptr, qy, M_ROWS, QKV_DIM, C_DIM);

    // 2) fused dual-softmax attention (both branches)
    attention_kernel<<<dim3(SEQ / 64, HEADS * 2, BATCH), 256, ATT_SMEM>>>();

    // 3) output projections + bias
    dim3 g2(C_DIM / 128, M_ROWS / 128);
    sgemm_nt<<<g2, 256>>>(ax, w_proj, b_proj, out,                     M_ROWS, C_DIM, C_DIM);
    sgemm_nt<<<g2, 256>>>(ay, w_proj, b_proj, out + M_ROWS * C_DIM,    M_ROWS, C_DIM, C_DIM);
}

// round 3
// speedup vs baseline: 1.2889x; 1.2889x over previous
#include <cuda_runtime.h>
#include <cuda_bf16.h>
#include <cstdint>

#define C_DIM   768
#define QKV_DIM 3072
#define BATCH   4
#define SEQ     1024
#define HEADS   12
#define HD      64
#define M_ROWS  (BATCH*SEQ)   // 4096

// -------- scratch (allocation-free: device globals) --------
__device__ float g_qkv_x[BATCH*SEQ*QKV_DIM];
__device__ float g_qkv_y[BATCH*SEQ*QKV_DIM];
__device__ float g_att_x[BATCH*SEQ*C_DIM];
__device__ float g_att_y[BATCH*SEQ*C_DIM];

// ============================================================
// helpers
// ============================================================
__device__ __forceinline__ uint32_t smem_u32(const void* p) {
    uint32_t a;
    asm("{ .reg .u64 t; cvta.to.shared.u64 t, %1; cvt.u32.u64 %0, t; }"
        : "=r"(a) : "l"(p));
    return a;
}

__device__ __forceinline__ void ldsm_x4(uint32_t addr, uint32_t& r0, uint32_t& r1,
                                        uint32_t& r2, uint32_t& r3) {
    asm volatile("ldmatrix.sync.aligned.m8n8.x4.shared.b16 {%0,%1,%2,%3}, [%4];"
                 : "=r"(r0), "=r"(r1), "=r"(r2), "=r"(r3) : "r"(addr));
}

__device__ __forceinline__ void mma_bf16(float* c, uint32_t a0, uint32_t a1,
                                         uint32_t a2, uint32_t a3,
                                         uint32_t b0, uint32_t b1) {
    asm volatile(
        "mma.sync.aligned.m16n8k16.row.col.f32.bf16.bf16.f32 "
        "{%0,%1,%2,%3}, {%4,%5,%6,%7}, {%8,%9}, {%0,%1,%2,%3};"
        : "+f"(c[0]), "+f"(c[1]), "+f"(c[2]), "+f"(c[3])
        : "r"(a0), "r"(a1), "r"(a2), "r"(a3), "r"(b0), "r"(b1));
}

__device__ __forceinline__ uint32_t pack_bf2(__nv_bfloat16 a, __nv_bfloat16 b) {
    return ((uint32_t)__bfloat16_as_ushort(b) << 16) | (uint32_t)__bfloat16_as_ushort(a);
}

// split fp32 float4 -> hi/lo bf16 limb pairs (2x uint2)
__device__ __forceinline__ void split4(float4 v, uint2& hi, uint2& lo) {
    __nv_bfloat16 h0 = __float2bfloat16_rn(v.x);
    __nv_bfloat16 h1 = __float2bfloat16_rn(v.y);
    __nv_bfloat16 h2 = __float2bfloat16_rn(v.z);
    __nv_bfloat16 h3 = __float2bfloat16_rn(v.w);
    __nv_bfloat16 l0 = __float2bfloat16_rn(v.x - __bfloat162float(h0));
    __nv_bfloat16 l1 = __float2bfloat16_rn(v.y - __bfloat162float(h1));
    __nv_bfloat16 l2 = __float2bfloat16_rn(v.z - __bfloat162float(h2));
    __nv_bfloat16 l3 = __float2bfloat16_rn(v.w - __bfloat162float(h3));
    hi.x = pack_bf2(h0, h1); hi.y = pack_bf2(h2, h3);
    lo.x = pack_bf2(l0, l1); lo.y = pack_bf2(l2, l3);
}

// ============================================================
// split-bf16 mma.sync GEMM: C[m,n] = sum_k A[m,k]*B[n,k] (+bias[n])
// BM=BN=128, BK=32 (fp32 k), 256 threads = 8 warps (2m x 4n),
// warp tile 64m x 32n, m16n8k16 HMMA, 3 limb MMAs (AhBh+AhBl+AlBh).
// smem: double-buffered [Ah Al Bh Bl], rows padded to 40 halves.
// ============================================================
#define LDH 40                          // halves per smem row (32 used + pad)
#define ARR (128 * LDH)                 // halves per limb array (5120)
#define STG (4 * ARR)                   // halves per stage (20480)
#define GEMM_SMEM (2 * STG * 2)         // bytes = 81920

__global__ __launch_bounds__(256, 1) void gemm_mma(
    const float* __restrict__ A, const float* __restrict__ B,
    const float* __restrict__ bias, float* __restrict__ C,
    int M, int N, int K)
{
    extern __shared__ __align__(16) __nv_bfloat16 sh[];
    const int tid  = threadIdx.x;
    const int wid  = tid >> 5;
    const int lane = tid & 31;
    const int m0 = blockIdx.y * 128, n0 = blockIdx.x * 128;
    const int wm = (wid >> 2) * 64;      // warp m offset (0/64)
    const int wn = (wid & 3) * 32;       // warp n offset
    const int S  = K / 32;

    const uint32_t sbase = smem_u32(sh);

    // per-thread ldmatrix row-address components (half units)
    const int a_row = (wm + (lane & 15)) * LDH + ((lane >> 4) << 3);
    const int b_row = (wn + ((lane >> 4) << 3) + (lane & 7)) * LDH + (((lane >> 3) & 1) << 3);

    float acc[4][4][4];   // [m-tile][n-tile][reg]
#pragma unroll
    for (int i = 0; i < 4; i++)
#pragma unroll
        for (int j = 0; j < 4; j++)
#pragma unroll
            for (int r = 0; r < 4; r++) acc[i][j][r] = 0.f;

    // gmem slot mapping: slot = u*256+tid; row=slot>>3, kc=(slot&7)*4
    const int g_row = tid >> 3;
    const int g_kc  = (tid & 7) << 2;

    float4 pa[4], pb[4];
    // ---- prefetch stage 0 ----
#pragma unroll
    for (int u = 0; u < 4; u++) {
        int row = g_row + u * 32;
        pa[u] = *(const float4*)(A + (size_t)(m0 + row) * K + g_kc);
        pb[u] = *(const float4*)(B + (size_t)(n0 + row) * K + g_kc);
    }
    // store stage 0
    {
        __nv_bfloat16* st = sh;
#pragma unroll
        for (int u = 0; u < 4; u++) {
            int row = g_row + u * 32;
            int off = row * LDH + g_kc;
            uint2 hi, lo;
            split4(pa[u], hi, lo);
            *(uint2*)(st + off)        = hi;
            *(uint2*)(st + ARR + off)  = lo;
            split4(pb[u], hi, lo);
            *(uint2*)(st + 2*ARR + off) = hi;
            *(uint2*)(st + 3*ARR + off) = lo;
        }
    }
    __syncthreads();

    for (int s = 0; s < S; s++) {
        const int cur = s & 1;
        // prefetch next stage into regs
        if (s + 1 < S) {
            const int kb = (s + 1) * 32;
#pragma unroll
            for (int u = 0; u < 4; u++) {
                int row = g_row + u * 32;
                pa[u] = *(const float4*)(A + (size_t)(m0 + row) * K + kb + g_kc);
                pb[u] = *(const float4*)(B + (size_t)(n0 + row) * K + kb + g_kc);
            }
        }

        // ---- compute stage s ----
        const uint32_t stg = sbase + (uint32_t)(cur * STG) * 2u;  // byte addr
#pragma unroll
        for (int ks = 0; ks < 2; ks++) {
            const int kofs = ks * 16;
            uint32_t ah[4][4], al[4][4];
#pragma unroll
            for (int mt = 0; mt < 4; mt++) {
                uint32_t ra = stg + (uint32_t)(a_row + mt * 16 * LDH + kofs) * 2u;
                ldsm_x4(ra,              ah[mt][0], ah[mt][1], ah[mt][2], ah[mt][3]);
                ldsm_x4(ra + ARR * 2u,   al[mt][0], al[mt][1], al[mt][2], al[mt][3]);
            }
            uint32_t bh[4][2], bl[4][2];
#pragma unroll
            for (int p = 0; p < 2; p++) {
                uint32_t rb = stg + (uint32_t)(b_row + p * 16 * LDH + kofs) * 2u + 2u * ARR * 2u;
                ldsm_x4(rb,             bh[p*2][0], bh[p*2][1], bh[p*2+1][0], bh[p*2+1][1]);
                ldsm_x4(rb + ARR * 2u,  bl[p*2][0], bl[p*2][1], bl[p*2+1][0], bl[p*2+1][1]);
            }
#pragma unroll
            for (int mt = 0; mt < 4; mt++)
#pragma unroll
                for (int nt = 0; nt < 4; nt++) {
                    mma_bf16(acc[mt][nt], ah[mt][0], ah[mt][1], ah[mt][2], ah[mt][3],
                             bh[nt][0], bh[nt][1]);
                    mma_bf16(acc[mt][nt], ah[mt][0], ah[mt][1], ah[mt][2], ah[mt][3],
                             bl[nt][0], bl[nt][1]);
                    mma_bf16(acc[mt][nt], al[mt][0], al[mt][1], al[mt][2], al[mt][3],
                             bh[nt][0], bh[nt][1]);
                }
        }
        __syncthreads();

        // store prefetched stage
        if (s + 1 < S) {
            __nv_bfloat16* st = sh + (size_t)((s + 1) & 1) * STG;
#pragma unroll
            for (int u = 0; u < 4; u++) {
                int row = g_row + u * 32;
                int off = row * LDH + g_kc;
                uint2 hi, lo;
                split4(pa[u], hi, lo);
                *(uint2*)(st + off)        = hi;
                *(uint2*)(st + ARR + off)  = lo;
                split4(pb[u], hi, lo);
                *(uint2*)(st + 2*ARR + off) = hi;
                *(uint2*)(st + 3*ARR + off) = lo;
            }
            __syncthreads();
        }
    }

    // ---- epilogue: fragments -> gmem (float2 stores, cols even) ----
#pragma unroll
    for (int mt = 0; mt < 4; mt++) {
        int row0 = m0 + wm + mt * 16 + (lane >> 2);
#pragma unroll
        for (int nt = 0; nt < 4; nt++) {
            int col = n0 + wn + nt * 8 + (lane & 3) * 2;
            float b0 = 0.f, b1 = 0.f;
            if (bias) { b0 = __ldg(bias + col); b1 = __ldg(bias + col + 1); }
            float2 v0 = make_float2(acc[mt][nt][0] + b0, acc[mt][nt][1] + b1);
            float2 v1 = make_float2(acc[mt][nt][2] + b0, acc[mt][nt][3] + b1);
            *(float2*)(C + (size_t)row0 * N + col)       = v0;
            *(float2*)(C + (size_t)(row0 + 8) * N + col) = v1;
        }
    }
}

// ============================================================
// Fused dual-softmax flash attention (unchanged, FFMA).
// ============================================================
#define SROW 68
#define ATT_SMEM (6 * 64 * SROW * 4)

__device__ __forceinline__ void softmax_update(
    const float s[4][4], float sgn,
    float m[4], float l[4], float O[4][4],
    float* __restrict__ P, int tx, int ty)
{
#pragma unroll
    for (int r = 0; r < 4; r++) {
        float sv[4];
#pragma unroll
        for (int c = 0; c < 4; c++) sv[c] = s[r][c] * sgn;
        float mx = fmaxf(fmaxf(sv[0], sv[1]), fmaxf(sv[2], sv[3]));
#pragma unroll
        for (int off = 8; off >= 1; off >>= 1)
            mx = fmaxf(mx, __shfl_xor_sync(0xffffffffu, mx, off));
        float mnew = fmaxf(m[r], mx);
        float corr = __expf(m[r] - mnew);
        float p[4], sum = 0.f;
#pragma unroll
        for (int c = 0; c < 4; c++) { p[c] = __expf(sv[c] - mnew); sum += p[c]; }
#pragma unroll
        for (int off = 8; off >= 1; off >>= 1)
            sum += __shfl_xor_sync(0xffffffffu, sum, off);
        l[r] = l[r] * corr + sum;
        m[r] = mnew;
#pragma unroll
        for (int c = 0; c < 4; c++) O[r][c] *= corr;
#pragma unroll
        for (int c = 0; c < 4; c++)
            P[(tx * 4 + c) * SROW + ty * 4 + r] = p[c];
    }
}

__global__ __launch_bounds__(256, 2) void attention_kernel()
{
    extern __shared__ float smf[];
    float* Q1t = smf;
    float* Q2t = smf + 1 * 64 * SROW;
    float* Kt  = smf + 2 * 64 * SROW;
    float* Vs  = smf + 3 * 64 * SROW;
    float* P1  = smf + 4 * 64 * SROW;
    float* P2  = smf + 5 * 64 * SROW;

    const int b    = blockIdx.z;
    const int h    = blockIdx.y >> 1;
    const int pair = blockIdx.y & 1;
    const int q0   = blockIdx.x * 64;
    const int tid  = threadIdx.x;
    const int tx   = tid & 15;
    const int ty   = tid >> 4;

    const float* bx = g_qkv_x + (size_t)b * SEQ * QKV_DIM;
    const float* by = g_qkv_y + (size_t)b * SEQ * QKV_DIM;
    const int hoff  = h * HD;

    const float *Q1src, *Q2src, *Ksrc;
    float* outp;
    if (pair == 0) { Q1src = bx + C_DIM; Q2src = by;  Ksrc = bx + 2 * C_DIM; outp = g_att_x; }
    else           { Q1src = by + C_DIM; Q2src = bx;  Ksrc = by + 2 * C_DIM; outp = g_att_y; }
    const float* Vsrc = bx + 3 * C_DIM;   // vy = vx in the reference

    for (int t = tid; t < 64 * 16; t += 256) {
        int r  = t >> 4;
        int d4 = (t & 15) << 2;
        float4 v1 = *(const float4*)(Q1src + (size_t)(q0 + r) * QKV_DIM + hoff + d4);
        float4 v2 = *(const float4*)(Q2src + (size_t)(q0 + r) * QKV_DIM + hoff + d4);
        Q1t[(d4+0)*SROW + r] = v1.x; Q1t[(d4+1)*SROW + r] = v1.y;
        Q1t[(d4+2)*SROW + r] = v1.z; Q1t[(d4+3)*SROW + r] = v1.w;
        Q2t[(d4+0)*SROW + r] = v2.x; Q2t[(d4+1)*SROW + r] = v2.y;
        Q2t[(d4+2)*SROW + r] = v2.z; Q2t[(d4+3)*SROW + r] = v2.w;
    }

    float O1[4][4], O2[4][4];
    float m1[4], l1[4], m2[4], l2[4];
#pragma unroll
    for (int r = 0; r < 4; r++) {
        m1[r] = -1e30f; m2[r] = -1e30f; l1[r] = 0.f; l2[r] = 0.f;
#pragma unroll
        for (int c = 0; c < 4; c++) { O1[r][c] = 0.f; O2[r][c] = 0.f; }
    }

    const float SC = 0.125f;

    for (int kt = 0; kt < 16; kt++) {
        const int j0 = kt * 64;
        __syncthreads();
        for (int t = tid; t < 64 * 16; t += 256) {
            int r  = t >> 4;
            int d4 = (t & 15) << 2;
            float4 kv = *(const float4*)(Ksrc + (size_t)(j0 + r) * QKV_DIM + hoff + d4);
            Kt[(d4+0)*SROW + r] = kv.x; Kt[(d4+1)*SROW + r] = kv.y;
            Kt[(d4+2)*SROW + r] = kv.z; Kt[(d4+3)*SROW + r] = kv.w;
            float4 vv = *(const float4*)(Vsrc + (size_t)(j0 + r) * QKV_DIM + hoff + d4);
            *(float4*)&Vs[r * SROW + d4] = vv;
        }
        __syncthreads();

        float s1[4][4], s2[4][4];
#pragma unroll
        for (int r = 0; r < 4; r++)
#pragma unroll
            for (int c = 0; c < 4; c++) { s1[r][c] = 0.f; s2[r][c] = 0.f; }

#pragma unroll 8
        for (int d = 0; d < 64; d++) {
            float4 q1 = *(const float4*)&Q1t[d * SROW + ty * 4];
            float4 q2 = *(const float4*)&Q2t[d * SROW + ty * 4];
            float4 kk = *(const float4*)&Kt [d * SROW + tx * 4];
            float qa1[4] = {q1.x, q1.y, q1.z, q1.w};
            float qa2[4] = {q2.x, q2.y, q2.z, q2.w};
            float ka [4] = {kk.x, kk.y, kk.z, kk.w};
#pragma unroll
            for (int r = 0; r < 4; r++)
#pragma unroll
                for (int c = 0; c < 4; c++) {
                    s1[r][c] += qa1[r] * ka[c];
                    s2[r][c] += qa2[r] * ka[c];
                }
        }

        softmax_update(s1,  SC, m1, l1, O1, P1, tx, ty);
        softmax_update(s2, -SC, m2, l2, O2, P2, tx, ty);
        __syncthreads();

#pragma unroll 8
        for (int j = 0; j < 64; j++) {
            float4 vv = *(const float4*)&Vs[j * SROW + tx * 4];
            float4 pa = *(const float4*)&P1[j * SROW + ty * 4];
            float4 pb = *(const float4*)&P2[j * SROW + ty * 4];
            float va[4]  = {vv.x, vv.y, vv.z, vv.w};
            float pa1[4] = {pa.x, pa.y, pa.z, pa.w};
            float pa2[4] = {pb.x, pb.y, pb.z, pb.w};
#pragma unroll
            for (int r = 0; r < 4; r++)
#pragma unroll
                for (int c = 0; c < 4; c++) {
                    O1[r][c] += pa1[r] * va[c];
                    O2[r][c] += pa2[r] * va[c];
                }
        }
    }

#pragma unroll
    for (int r = 0; r < 4; r++) {
        float inv1 = 1.f / l1[r];
        float inv2 = 1.f / l2[r];
        float4 o;
        o.x = O1[r][0] * inv1 + O2[r][0] * inv2;
        o.y = O1[r][1] * inv1 + O2[r][1] * inv2;
        o.z = O1[r][2] * inv1 + O2[r][2] * inv2;
        o.w = O1[r][3] * inv1 + O2[r][3] * inv2;
        *(float4*)(outp + (size_t)b * SEQ * C_DIM
                        + (size_t)(q0 + ty * 4 + r) * C_DIM
                        + hoff + tx * 4) = o;
    }
}

// ============================================================
extern "C" void kernel_launch(void* const* d_in, const int* in_sizes, int n_in,
                              void* d_out, int out_size)
{
    const float* x      = (const float*)d_in[0];
    const float* y      = (const float*)d_in[1];
    const float* w_qkv  = (const float*)d_in[2];
    const float* w_proj = (const float*)d_in[3];
    const float* b_proj = (const float*)d_in[4];
    float* out = (float*)d_out;

    float *qx, *qy, *ax, *ay;
    cudaGetSymbolAddress((void**)&qx, g_qkv_x);
    cudaGetSymbolAddress((void**)&qy, g_qkv_y);
    cudaGetSymbolAddress((void**)&ax, g_att_x);
    cudaGetSymbolAddress((void**)&ay, g_att_y);

    cudaFuncSetAttribute(gemm_mma,
                         cudaFuncAttributeMaxDynamicSharedMemorySize, GEMM_SMEM);
    cudaFuncSetAttribute(attention_kernel,
                         cudaFuncAttributeMaxDynamicSharedMemorySize, ATT_SMEM);

    // 1) QKV projections (split-bf16 HMMA)
    dim3 g1(QKV_DIM / 128, M_ROWS / 128);
    gemm_mma<<<g1, 256, GEMM_SMEM>>>(x, w_qkv, nullptr, qx, M_ROWS, QKV_DIM, C_DIM);
    gemm_mma<<<g1, 256, GEMM_SMEM>>>(y, w_qkv, nullptr, qy, M_ROWS, QKV_DIM, C_DIM);

    // 2) fused dual-softmax attention
    attention_kernel<<<dim3(SEQ / 64, HEADS * 2, BATCH), 256, ATT_SMEM>>>();

    // 3) output projections + bias (split-bf16 HMMA)
    dim3 g2(C_DIM / 128, M_ROWS / 128);
    gemm_mma<<<g2, 256, GEMM_SMEM>>>(ax, w_proj, b_proj, out,                  M_ROWS, C_DIM, C_DIM);
    gemm_mma<<<g2, 256, GEMM_SMEM>>>(ay, w_proj, b_proj, out + M_ROWS * C_DIM, M_ROWS, C_DIM, C_DIM);
}

// round 4
// speedup vs baseline: 2.1631x; 1.6783x over previous
#include <cuda_runtime.h>
#include <cuda_bf16.h>
#include <cstdint>

#define C_DIM   768
#define QKV_DIM 3072
#define BATCH   4
#define SEQ     1024
#define HEADS   12
#define HD      64
#define M_ROWS  (BATCH*SEQ)   // 4096

// -------- scratch (allocation-free: device globals) --------
__device__ float g_qkv_x[BATCH*SEQ*QKV_DIM];
__device__ float g_qkv_y[BATCH*SEQ*QKV_DIM];
__device__ float g_att_x[BATCH*SEQ*C_DIM];
__device__ float g_att_y[BATCH*SEQ*C_DIM];

// ============================================================
// helpers
// ============================================================
__device__ __forceinline__ uint32_t smem_u32(const void* p) {
    uint32_t a;
    asm("{ .reg .u64 t; cvta.to.shared.u64 t, %1; cvt.u32.u64 %0, t; }"
        : "=r"(a) : "l"(p));
    return a;
}

__device__ __forceinline__ void ldsm_x4(uint32_t addr, uint32_t& r0, uint32_t& r1,
                                        uint32_t& r2, uint32_t& r3) {
    asm volatile("ldmatrix.sync.aligned.m8n8.x4.shared.b16 {%0,%1,%2,%3}, [%4];"
                 : "=r"(r0), "=r"(r1), "=r"(r2), "=r"(r3) : "r"(addr));
}

__device__ __forceinline__ void mma_bf16(float* c, uint32_t a0, uint32_t a1,
                                         uint32_t a2, uint32_t a3,
                                         uint32_t b0, uint32_t b1) {
    asm volatile(
        "mma.sync.aligned.m16n8k16.row.col.f32.bf16.bf16.f32 "
        "{%0,%1,%2,%3}, {%4,%5,%6,%7}, {%8,%9}, {%0,%1,%2,%3};"
        : "+f"(c[0]), "+f"(c[1]), "+f"(c[2]), "+f"(c[3])
        : "r"(a0), "r"(a1), "r"(a2), "r"(a3), "r"(b0), "r"(b1));
}

__device__ __forceinline__ uint32_t pack_bf2(__nv_bfloat16 a, __nv_bfloat16 b) {
    return ((uint32_t)__bfloat16_as_ushort(b) << 16) | (uint32_t)__bfloat16_as_ushort(a);
}

// split fp32 float4 -> hi/lo bf16 limb pairs (2x uint2)
__device__ __forceinline__ void split4(float4 v, uint2& hi, uint2& lo) {
    __nv_bfloat16 h0 = __float2bfloat16_rn(v.x);
    __nv_bfloat16 h1 = __float2bfloat16_rn(v.y);
    __nv_bfloat16 h2 = __float2bfloat16_rn(v.z);
    __nv_bfloat16 h3 = __float2bfloat16_rn(v.w);
    __nv_bfloat16 l0 = __float2bfloat16_rn(v.x - __bfloat162float(h0));
    __nv_bfloat16 l1 = __float2bfloat16_rn(v.y - __bfloat162float(h1));
    __nv_bfloat16 l2 = __float2bfloat16_rn(v.z - __bfloat162float(h2));
    __nv_bfloat16 l3 = __float2bfloat16_rn(v.w - __bfloat162float(h3));
    hi.x = pack_bf2(h0, h1); hi.y = pack_bf2(h2, h3);
    lo.x = pack_bf2(l0, l1); lo.y = pack_bf2(l2, l3);
}

// ============================================================
// split-bf16 mma.sync GEMM (z-batched over two A/C pairs)
// ============================================================
#define LDH 40
#define ARR (128 * LDH)
#define STG (4 * ARR)
#define GEMM_SMEM (2 * STG * 2)

__global__ __launch_bounds__(256, 1) void gemm_mma(
    const float* __restrict__ A0, const float* __restrict__ A1,
    const float* __restrict__ B, const float* __restrict__ bias,
    float* __restrict__ C0, float* __restrict__ C1,
    int M, int N, int K)
{
    extern __shared__ __align__(16) __nv_bfloat16 sh[];
    const int tid  = threadIdx.x;
    const int wid  = tid >> 5;
    const int lane = tid & 31;
    const int m0 = blockIdx.y * 128, n0 = blockIdx.x * 128;
    const int wm = (wid >> 2) * 64;
    const int wn = (wid & 3) * 32;
    const int S  = K / 32;

    const float* A = blockIdx.z ? A1 : A0;
    float*       C = blockIdx.z ? C1 : C0;

    const uint32_t sbase = smem_u32(sh);
    const int a_row = (wm + (lane & 15)) * LDH + ((lane >> 4) << 3);
    const int b_row = (wn + ((lane >> 4) << 3) + (lane & 7)) * LDH + (((lane >> 3) & 1) << 3);

    float acc[4][4][4];
#pragma unroll
    for (int i = 0; i < 4; i++)
#pragma unroll
        for (int j = 0; j < 4; j++)
#pragma unroll
            for (int r = 0; r < 4; r++) acc[i][j][r] = 0.f;

    const int g_row = tid >> 3;
    const int g_kc  = (tid & 7) << 2;

    float4 pa[4], pb[4];
#pragma unroll
    for (int u = 0; u < 4; u++) {
        int row = g_row + u * 32;
        pa[u] = *(const float4*)(A + (size_t)(m0 + row) * K + g_kc);
        pb[u] = *(const float4*)(B + (size_t)(n0 + row) * K + g_kc);
    }
    {
        __nv_bfloat16* st = sh;
#pragma unroll
        for (int u = 0; u < 4; u++) {
            int row = g_row + u * 32;
            int off = row * LDH + g_kc;
            uint2 hi, lo;
            split4(pa[u], hi, lo);
            *(uint2*)(st + off)        = hi;
            *(uint2*)(st + ARR + off)  = lo;
            split4(pb[u], hi, lo);
            *(uint2*)(st + 2*ARR + off) = hi;
            *(uint2*)(st + 3*ARR + off) = lo;
        }
    }
    __syncthreads();

    for (int s = 0; s < S; s++) {
        const int cur = s & 1;
        if (s + 1 < S) {
            const int kb = (s + 1) * 32;
#pragma unroll
            for (int u = 0; u < 4; u++) {
                int row = g_row + u * 32;
                pa[u] = *(const float4*)(A + (size_t)(m0 + row) * K + kb + g_kc);
                pb[u] = *(const float4*)(B + (size_t)(n0 + row) * K + kb + g_kc);
            }
        }

        const uint32_t stg = sbase + (uint32_t)(cur * STG) * 2u;
#pragma unroll
        for (int ks = 0; ks < 2; ks++) {
            const int kofs = ks * 16;
            uint32_t ah[4][4], al[4][4];
#pragma unroll
            for (int mt = 0; mt < 4; mt++) {
                uint32_t ra = stg + (uint32_t)(a_row + mt * 16 * LDH + kofs) * 2u;
                ldsm_x4(ra,              ah[mt][0], ah[mt][1], ah[mt][2], ah[mt][3]);
                ldsm_x4(ra + ARR * 2u,   al[mt][0], al[mt][1], al[mt][2], al[mt][3]);
            }
            uint32_t bh[4][2], bl[4][2];
#pragma unroll
            for (int p = 0; p < 2; p++) {
                uint32_t rb = stg + (uint32_t)(b_row + p * 16 * LDH + kofs) * 2u + 2u * ARR * 2u;
                ldsm_x4(rb,             bh[p*2][0], bh[p*2][1], bh[p*2+1][0], bh[p*2+1][1]);
                ldsm_x4(rb + ARR * 2u,  bl[p*2][0], bl[p*2][1], bl[p*2+1][0], bl[p*2+1][1]);
            }
#pragma unroll
            for (int mt = 0; mt < 4; mt++)
#pragma unroll
                for (int nt = 0; nt < 4; nt++) {
                    mma_bf16(acc[mt][nt], ah[mt][0], ah[mt][1], ah[mt][2], ah[mt][3],
                             bh[nt][0], bh[nt][1]);
                    mma_bf16(acc[mt][nt], ah[mt][0], ah[mt][1], ah[mt][2], ah[mt][3],
                             bl[nt][0], bl[nt][1]);
                    mma_bf16(acc[mt][nt], al[mt][0], al[mt][1], al[mt][2], al[mt][3],
                             bh[nt][0], bh[nt][1]);
                }
        }
        __syncthreads();

        if (s + 1 < S) {
            __nv_bfloat16* st = sh + (size_t)((s + 1) & 1) * STG;
#pragma unroll
            for (int u = 0; u < 4; u++) {
                int row = g_row + u * 32;
                int off = row * LDH + g_kc;
                uint2 hi, lo;
                split4(pa[u], hi, lo);
                *(uint2*)(st + off)        = hi;
                *(uint2*)(st + ARR + off)  = lo;
                split4(pb[u], hi, lo);
                *(uint2*)(st + 2*ARR + off) = hi;
                *(uint2*)(st + 3*ARR + off) = lo;
            }
            __syncthreads();
        }
    }

#pragma unroll
    for (int mt = 0; mt < 4; mt++) {
        int row0 = m0 + wm + mt * 16 + (lane >> 2);
#pragma unroll
        for (int nt = 0; nt < 4; nt++) {
            int col = n0 + wn + nt * 8 + (lane & 3) * 2;
            float b0 = 0.f, b1 = 0.f;
            if (bias) { b0 = __ldg(bias + col); b1 = __ldg(bias + col + 1); }
            float2 v0 = make_float2(acc[mt][nt][0] + b0, acc[mt][nt][1] + b1);
            float2 v1 = make_float2(acc[mt][nt][2] + b0, acc[mt][nt][3] + b1);
            *(float2*)(C + (size_t)row0 * N + col)       = v0;
            *(float2*)(C + (size_t)(row0 + 8) * N + col) = v1;
        }
    }
}

// ============================================================
// Dual-softmax flash attention on mma.sync (split-bf16).
// CTA: 128 q-rows x (b, h, pair). 8 warps x 16 rows.
// Q pre-scaled by +/- hd^-0.5 at limb split; P repacked C->A in regs.
// ============================================================
#define AQS 72                           // halves per row (64 + 8 pad)
#define OQ1H 0
#define OQ1L (128*AQS)
#define OQ2H (2*128*AQS)
#define OQ2L (3*128*AQS)
#define OKH  (4*128*AQS)                 // 36864
#define OKL  (OKH + 64*AQS)
#define OVH  (OKH + 2*64*AQS)
#define OVL  (OKH + 3*64*AQS)
#define ATT_SMEM ((OKH + 4*64*AQS) * 2)  // 110592 bytes

__global__ __launch_bounds__(256, 1) void attention_mma()
{
    extern __shared__ __align__(16) __nv_bfloat16 sh[];
    const uint32_t sb = smem_u32(sh);
    const int tid  = threadIdx.x;
    const int wid  = tid >> 5;
    const int lane = tid & 31;
    const int wm   = wid * 16;

    const int b    = blockIdx.z;
    const int h    = blockIdx.y >> 1;
    const int pair = blockIdx.y & 1;
    const int q0   = blockIdx.x * 128;

    const float* bx = g_qkv_x + (size_t)b * SEQ * QKV_DIM;
    const float* by = g_qkv_y + (size_t)b * SEQ * QKV_DIM;
    const int hoff  = h * HD;

    const float *Q1src, *Q2src, *Ksrc;
    float* outp;
    if (pair == 0) { Q1src = bx + C_DIM; Q2src = by;  Ksrc = bx + 2 * C_DIM; outp = g_att_x; }
    else           { Q1src = by + C_DIM; Q2src = bx;  Ksrc = by + 2 * C_DIM; outp = g_att_y; }
    const float* Vsrc = bx + 3 * C_DIM;   // vy = vx in the reference

    // ---- load Q tiles as pre-scaled limbs ----
#pragma unroll
    for (int u = 0; u < 8; u++) {
        int idx = u * 256 + tid;
        int row = idx >> 4;
        int c4  = (idx & 15) << 2;
        float4 v1 = *(const float4*)(Q1src + (size_t)(q0 + row) * QKV_DIM + hoff + c4);
        float4 v2 = *(const float4*)(Q2src + (size_t)(q0 + row) * QKV_DIM + hoff + c4);
        v1.x *= 0.125f; v1.y *= 0.125f; v1.z *= 0.125f; v1.w *= 0.125f;
        v2.x *= -0.125f; v2.y *= -0.125f; v2.z *= -0.125f; v2.w *= -0.125f;
        uint2 hi, lo;
        int off = row * AQS + c4;
        split4(v1, hi, lo);
        *(uint2*)(sh + OQ1H + off) = hi;
        *(uint2*)(sh + OQ1L + off) = lo;
        split4(v2, hi, lo);
        *(uint2*)(sh + OQ2H + off) = hi;
        *(uint2*)(sh + OQ2L + off) = lo;
    }
    __syncthreads();

    // accumulators / softmax state
    float o1[8][4], o2[8][4];
#pragma unroll
    for (int d = 0; d < 8; d++)
#pragma unroll
        for (int r = 0; r < 4; r++) { o1[d][r] = 0.f; o2[d][r] = 0.f; }
    float m1lo = -1e30f, m1hi = -1e30f, l1lo = 0.f, l1hi = 0.f;
    float m2lo = -1e30f, m2hi = -1e30f, l2lo = 0.f, l2hi = 0.f;

    // fragment address bases (byte offsets added to sb)
    const uint32_t a_base = (uint32_t)((wm + (lane & 15)) * AQS + ((lane >> 4) << 3)) * 2u;
    const uint32_t b_base = (uint32_t)((((lane >> 4) << 3) + (lane & 7)) * AQS
                                       + (((lane >> 3) & 1) << 3)) * 2u;

    for (int kt = 0; kt < 16; kt++) {
        const int j0 = kt * 64;
        if (kt) __syncthreads();

        // ---- K tile -> limbs [j][d] ----
#pragma unroll
        for (int u = 0; u < 4; u++) {
            int idx = u * 256 + tid;
            int row = idx >> 4;
            int c4  = (idx & 15) << 2;
            float4 kv = *(const float4*)(Ksrc + (size_t)(j0 + row) * QKV_DIM + hoff + c4);
            uint2 hi, lo;
            split4(kv, hi, lo);
            int off = row * AQS + c4;
            *(uint2*)(sh + OKH + off) = hi;
            *(uint2*)(sh + OKL + off) = lo;
        }
        // ---- V tile -> transposed limbs [d][j] ----
        {
            int jp = tid & 31;        // j pair
            int d0 = (tid >> 5) * 8;  // 8 d per thread
            const float* v0p = Vsrc + (size_t)(j0 + 2 * jp)     * QKV_DIM + hoff + d0;
            const float* v1p = Vsrc + (size_t)(j0 + 2 * jp + 1) * QKV_DIM + hoff + d0;
            float4 va0 = *(const float4*)(v0p);
            float4 va1 = *(const float4*)(v0p + 4);
            float4 vb0 = *(const float4*)(v1p);
            float4 vb1 = *(const float4*)(v1p + 4);
            float f0[8] = {va0.x, va0.y, va0.z, va0.w, va1.x, va1.y, va1.z, va1.w};
            float f1[8] = {vb0.x, vb0.y, vb0.z, vb0.w, vb1.x, vb1.y, vb1.z, vb1.w};
#pragma unroll
            for (int i = 0; i < 8; i++) {
                __nv_bfloat16 h0 = __float2bfloat16_rn(f0[i]);
                __nv_bfloat16 h1 = __float2bfloat16_rn(f1[i]);
                __nv_bfloat16 e0 = __float2bfloat16_rn(f0[i] - __bfloat162float(h0));
                __nv_bfloat16 e1 = __float2bfloat16_rn(f1[i] - __bfloat162float(h1));
                *(uint32_t*)(sh + OVH + (d0 + i) * AQS + 2 * jp) = pack_bf2(h0, h1);
                *(uint32_t*)(sh + OVL + (d0 + i) * AQS + 2 * jp) = pack_bf2(e0, e1);
            }
        }
        __syncthreads();

        // ---- S = Q K^T (both streams, 3 limbs) ----
        float s1[8][4], s2[8][4];
#pragma unroll
        for (int n = 0; n < 8; n++)
#pragma unroll
            for (int r = 0; r < 4; r++) { s1[n][r] = 0.f; s2[n][r] = 0.f; }

#pragma unroll
        for (int ks = 0; ks < 4; ks++) {
            const uint32_t kofs = (uint32_t)(ks * 16) * 2u;
            uint32_t a1h[4], a1l[4], a2h[4], a2l[4];
            ldsm_x4(sb + OQ1H*2u + a_base + kofs, a1h[0], a1h[1], a1h[2], a1h[3]);
            ldsm_x4(sb + OQ1L*2u + a_base + kofs, a1l[0], a1l[1], a1l[2], a1l[3]);
            ldsm_x4(sb + OQ2H*2u + a_base + kofs, a2h[0], a2h[1], a2h[2], a2h[3]);
            ldsm_x4(sb + OQ2L*2u + a_base + kofs, a2l[0], a2l[1], a2l[2], a2l[3]);
#pragma unroll
            for (int jt = 0; jt < 4; jt++) {
                uint32_t rb = sb + b_base + (uint32_t)(jt * 16 * AQS) * 2u + kofs;
                uint32_t bh[2][2], bl[2][2];
                ldsm_x4(rb + OKH*2u, bh[0][0], bh[0][1], bh[1][0], bh[1][1]);
                ldsm_x4(rb + OKL*2u, bl[0][0], bl[0][1], bl[1][0], bl[1][1]);
#pragma unroll
                for (int q = 0; q < 2; q++) {
                    int nt = jt * 2 + q;
                    mma_bf16(s1[nt], a1h[0], a1h[1], a1h[2], a1h[3], bh[q][0], bh[q][1]);
                    mma_bf16(s1[nt], a1h[0], a1h[1], a1h[2], a1h[3], bl[q][0], bl[q][1]);
                    mma_bf16(s1[nt], a1l[0], a1l[1], a1l[2], a1l[3], bh[q][0], bh[q][1]);
                    mma_bf16(s2[nt], a2h[0], a2h[1], a2h[2], a2h[3], bh[q][0], bh[q][1]);
                    mma_bf16(s2[nt], a2h[0], a2h[1], a2h[2], a2h[3], bl[q][0], bl[q][1]);
                    mma_bf16(s2[nt], a2l[0], a2l[1], a2l[2], a2l[3], bh[q][0], bh[q][1]);
                }
            }
        }

        // ---- online softmax (per stream), produce P limb A-fragments ----
        uint32_t p1h[8][2], p1l[8][2], p2h[8][2], p2l[8][2];
        {
            // stream 1
            float mxlo = -1e30f, mxhi = -1e30f;
#pragma unroll
            for (int n = 0; n < 8; n++) {
                mxlo = fmaxf(mxlo, fmaxf(s1[n][0], s1[n][1]));
                mxhi = fmaxf(mxhi, fmaxf(s1[n][2], s1[n][3]));
            }
            mxlo = fmaxf(mxlo, __shfl_xor_sync(0xffffffffu, mxlo, 1));
            mxlo = fmaxf(mxlo, __shfl_xor_sync(0xffffffffu, mxlo, 2));
            mxhi = fmaxf(mxhi, __shfl_xor_sync(0xffffffffu, mxhi, 1));
            mxhi = fmaxf(mxhi, __shfl_xor_sync(0xffffffffu, mxhi, 2));
            float mnlo = fmaxf(m1lo, mxlo), mnhi = fmaxf(m1hi, mxhi);
            float clo = __expf(m1lo - mnlo), chi = __expf(m1hi - mnhi);
            m1lo = mnlo; m1hi = mnhi;
            float sl = 0.f, shh = 0.f;
#pragma unroll
            for (int n = 0; n < 8; n++) {
                float p0 = __expf(s1[n][0] - mnlo);
                float p1 = __expf(s1[n][1] - mnlo);
                float p2 = __expf(s1[n][2] - mnhi);
                float p3 = __expf(s1[n][3] - mnhi);
                sl += p0 + p1; shh += p2 + p3;
                __nv_bfloat16 h0 = __float2bfloat16_rn(p0), h1 = __float2bfloat16_rn(p1);
                __nv_bfloat16 h2 = __float2bfloat16_rn(p2), h3 = __float2bfloat16_rn(p3);
                p1h[n][0] = pack_bf2(h0, h1);
                p1h[n][1] = pack_bf2(h2, h3);
                p1l[n][0] = pack_bf2(__float2bfloat16_rn(p0 - __bfloat162float(h0)),
                                     __float2bfloat16_rn(p1 - __bfloat162float(h1)));
                p1l[n][1] = pack_bf2(__float2bfloat16_rn(p2 - __bfloat162float(h2)),
                                     __float2bfloat16_rn(p3 - __bfloat162float(h3)));
            }
            sl  += __shfl_xor_sync(0xffffffffu, sl, 1);
            sl  += __shfl_xor_sync(0xffffffffu, sl, 2);
            shh += __shfl_xor_sync(0xffffffffu, shh, 1);
            shh += __shfl_xor_sync(0xffffffffu, shh, 2);
            l1lo = l1lo * clo + sl; l1hi = l1hi * chi + shh;
#pragma unroll
            for (int d = 0; d < 8; d++) {
                o1[d][0] *= clo; o1[d][1] *= clo;
                o1[d][2] *= chi; o1[d][3] *= chi;
            }
        }
        {
            // stream 2
            float mxlo = -1e30f, mxhi = -1e30f;
#pragma unroll
            for (int n = 0; n < 8; n++) {
                mxlo = fmaxf(mxlo, fmaxf(s2[n][0], s2[n][1]));
                mxhi = fmaxf(mxhi, fmaxf(s2[n][2], s2[n][3]));
            }
            mxlo = fmaxf(mxlo, __shfl_xor_sync(0xffffffffu, mxlo, 1));
            mxlo = fmaxf(mxlo, __shfl_xor_sync(0xffffffffu, mxlo, 2));
            mxhi = fmaxf(mxhi, __shfl_xor_sync(0xffffffffu, mxhi, 1));
            mxhi = fmaxf(mxhi, __shfl_xor_sync(0xffffffffu, mxhi, 2));
            float mnlo = fmaxf(m2lo, mxlo), mnhi = fmaxf(m2hi, mxhi);
            float clo = __expf(m2lo - mnlo), chi = __expf(m2hi - mnhi);
            m2lo = mnlo; m2hi = mnhi;
            float sl = 0.f, shh = 0.f;
#pragma unroll
            for (int n = 0; n < 8; n++) {
                float p0 = __expf(s2[n][0] - mnlo);
                float p1 = __expf(s2[n][1] - mnlo);
                float p2 = __expf(s2[n][2] - mnhi);
                float p3 = __expf(s2[n][3] - mnhi);
                sl += p0 + p1; shh += p2 + p3;
                __nv_bfloat16 h0 = __float2bfloat16_rn(p0), h1 = __float2bfloat16_rn(p1);
                __nv_bfloat16 h2 = __float2bfloat16_rn(p2), h3 = __float2bfloat16_rn(p3);
                p2h[n][0] = pack_bf2(h0, h1);
                p2h[n][1] = pack_bf2(h2, h3);
                p2l[n][0] = pack_bf2(__float2bfloat16_rn(p0 - __bfloat162float(h0)),
                                     __float2bfloat16_rn(p1 - __bfloat162float(h1)));
                p2l[n][1] = pack_bf2(__float2bfloat16_rn(p2 - __bfloat162float(h2)),
                                     __float2bfloat16_rn(p3 - __bfloat162float(h3)));
            }
            sl  += __shfl_xor_sync(0xffffffffu, sl, 1);
            sl  += __shfl_xor_sync(0xffffffffu, sl, 2);
            shh += __shfl_xor_sync(0xffffffffu, shh, 1);
            shh += __shfl_xor_sync(0xffffffffu, shh, 2);
            l2lo = l2lo * clo + sl; l2hi = l2hi * chi + shh;
#pragma unroll
            for (int d = 0; d < 8; d++) {
                o2[d][0] *= clo; o2[d][1] *= clo;
                o2[d][2] *= chi; o2[d][3] *= chi;
            }
        }

        // ---- O += P V (A-fragments repacked from S C-fragments) ----
#pragma unroll
        for (int ks = 0; ks < 4; ks++) {
            uint32_t a1hf[4] = { p1h[2*ks][0], p1h[2*ks][1], p1h[2*ks+1][0], p1h[2*ks+1][1] };
            uint32_t a1lf[4] = { p1l[2*ks][0], p1l[2*ks][1], p1l[2*ks+1][0], p1l[2*ks+1][1] };
            uint32_t a2hf[4] = { p2h[2*ks][0], p2h[2*ks][1], p2h[2*ks+1][0], p2h[2*ks+1][1] };
            uint32_t a2lf[4] = { p2l[2*ks][0], p2l[2*ks][1], p2l[2*ks+1][0], p2l[2*ks+1][1] };
            const uint32_t kofs = (uint32_t)(ks * 16) * 2u;
#pragma unroll
            for (int dt2 = 0; dt2 < 4; dt2++) {
                uint32_t rb = sb + b_base + (uint32_t)(dt2 * 16 * AQS) * 2u + kofs;
                uint32_t vh[2][2], vl[2][2];
                ldsm_x4(rb + OVH*2u, vh[0][0], vh[0][1], vh[1][0], vh[1][1]);
                ldsm_x4(rb + OVL*2u, vl[0][0], vl[0][1], vl[1][0], vl[1][1]);
#pragma unroll
                for (int q = 0; q < 2; q++) {
                    int dt = dt2 * 2 + q;
                    mma_bf16(o1[dt], a1hf[0], a1hf[1], a1hf[2], a1hf[3], vh[q][0], vh[q][1]);
                    mma_bf16(o1[dt], a1hf[0], a1hf[1], a1hf[2], a1hf[3], vl[q][0], vl[q][1]);
                    mma_bf16(o1[dt], a1lf[0], a1lf[1], a1lf[2], a1lf[3], vh[q][0], vh[q][1]);
                    mma_bf16(o2[dt], a2hf[0], a2hf[1], a2hf[2], a2hf[3], vh[q][0], vh[q][1]);
                    mma_bf16(o2[dt], a2hf[0], a2hf[1], a2hf[2], a2hf[3], vl[q][0], vl[q][1]);
                    mma_bf16(o2[dt], a2lf[0], a2lf[1], a2lf[2], a2lf[3], vh[q][0], vh[q][1]);
                }
            }
        }
    }

    // ---- epilogue: out = O1/l1 + O2/l2 ----
    const float i1lo = 1.f / l1lo, i1hi = 1.f / l1hi;
    const float i2lo = 1.f / l2lo, i2hi = 1.f / l2hi;
    float* obase = outp + (size_t)b * SEQ * C_DIM;
    const int r0 = q0 + wm + (lane >> 2);
    const int cb = hoff + (lane & 3) * 2;
#pragma unroll
    for (int dt = 0; dt < 8; dt++) {
        int col = cb + dt * 8;
        float2 vlo = make_float2(o1[dt][0] * i1lo + o2[dt][0] * i2lo,
                                 o1[dt][1] * i1lo + o2[dt][1] * i2lo);
        float2 vhi = make_float2(o1[dt][2] * i1hi + o2[dt][2] * i2hi,
                                 o1[dt][3] * i1hi + o2[dt][3] * i2hi);
        *(float2*)(obase + (size_t)r0 * C_DIM + col)       = vlo;
        *(float2*)(obase + (size_t)(r0 + 8) * C_DIM + col) = vhi;
    }
}

// ============================================================
extern "C" void kernel_launch(void* const* d_in, const int* in_sizes, int n_in,
                              void* d_out, int out_size)
{
    const float* x      = (const float*)d_in[0];
    const float* y      = (const float*)d_in[1];
    const float* w_qkv  = (const float*)d_in[2];
    const float* w_proj = (const float*)d_in[3];
    const float* b_proj = (const float*)d_in[4];
    float* out = (float*)d_out;

    float *qx, *qy, *ax, *ay;
    cudaGetSymbolAddress((void**)&qx, g_qkv_x);
    cudaGetSymbolAddress((void**)&qy, g_qkv_y);
    cudaGetSymbolAddress((void**)&ax, g_att_x);
    cudaGetSymbolAddress((void**)&ay, g_att_y);

    cudaFuncSetAttribute(gemm_mma,
                         cudaFuncAttributeMaxDynamicSharedMemorySize, GEMM_SMEM);
    cudaFuncSetAttribute(attention_mma,
                         cudaFuncAttributeMaxDynamicSharedMemorySize, ATT_SMEM);

    // 1) QKV projections, x and y batched in z
    dim3 g1(QKV_DIM / 128, M_ROWS / 128, 2);
    gemm_mma<<<g1, 256, GEMM_SMEM>>>(x, y, w_qkv, nullptr, qx, qy,
                                     M_ROWS, QKV_DIM, C_DIM);

    // 2) fused dual-softmax attention (mma.sync)
    attention_mma<<<dim3(SEQ / 128, HEADS * 2, BATCH), 256, ATT_SMEM>>>();

    // 3) output projections + bias, both branches batched in z
    dim3 g2(C_DIM / 128, M_ROWS / 128, 2);
    gemm_mma<<<g2, 256, GEMM_SMEM>>>(ax, ay, w_proj, b_proj,
                                     out, out + (size_t)M_ROWS * C_DIM,
                                     M_ROWS, C_DIM, C_DIM);
}

// round 5
// speedup vs baseline: 2.3888x; 1.1043x over previous
#include <cuda_runtime.h>
#include <cuda_bf16.h>
#include <cstdint>

#define C_DIM   768
#define QKV_DIM 3072
#define BATCH   4
#define SEQ     1024
#define HEADS   12
#define HD      64
#define M_ROWS  (BATCH*SEQ)   // 4096

// -------- scratch (allocation-free: device globals) --------
__device__ float g_qkv_x[BATCH*SEQ*QKV_DIM];
__device__ float g_qkv_y[BATCH*SEQ*QKV_DIM];
__device__ float g_att_x[BATCH*SEQ*C_DIM];
__device__ float g_att_y[BATCH*SEQ*C_DIM];

// ============================================================
// helpers
// ============================================================
__device__ __forceinline__ uint32_t smem_u32(const void* p) {
    uint32_t a;
    asm("{ .reg .u64 t; cvta.to.shared.u64 t, %1; cvt.u32.u64 %0, t; }"
        : "=r"(a) : "l"(p));
    return a;
}

__device__ __forceinline__ void ldsm_x4(uint32_t addr, uint32_t& r0, uint32_t& r1,
                                        uint32_t& r2, uint32_t& r3) {
    asm volatile("ldmatrix.sync.aligned.m8n8.x4.shared.b16 {%0,%1,%2,%3}, [%4];"
                 : "=r"(r0), "=r"(r1), "=r"(r2), "=r"(r3) : "r"(addr));
}

__device__ __forceinline__ void mma_bf16(float* c, const uint32_t* a,
                                         uint32_t b0, uint32_t b1) {
    asm volatile(
        "mma.sync.aligned.m16n8k16.row.col.f32.bf16.bf16.f32 "
        "{%0,%1,%2,%3}, {%4,%5,%6,%7}, {%8,%9}, {%0,%1,%2,%3};"
        : "+f"(c[0]), "+f"(c[1]), "+f"(c[2]), "+f"(c[3])
        : "r"(a[0]), "r"(a[1]), "r"(a[2]), "r"(a[3]), "r"(b0), "r"(b1));
}

__device__ __forceinline__ uint32_t pack_bf2(__nv_bfloat16 a, __nv_bfloat16 b) {
    return ((uint32_t)__bfloat16_as_ushort(b) << 16) | (uint32_t)__bfloat16_as_ushort(a);
}

// split fp32 float4 -> hi/lo bf16 limb pairs (2x uint2)
__device__ __forceinline__ void split4(float4 v, uint2& hi, uint2& lo) {
    __nv_bfloat16 h0 = __float2bfloat16_rn(v.x);
    __nv_bfloat16 h1 = __float2bfloat16_rn(v.y);
    __nv_bfloat16 h2 = __float2bfloat16_rn(v.z);
    __nv_bfloat16 h3 = __float2bfloat16_rn(v.w);
    __nv_bfloat16 l0 = __float2bfloat16_rn(v.x - __bfloat162float(h0));
    __nv_bfloat16 l1 = __float2bfloat16_rn(v.y - __bfloat162float(h1));
    __nv_bfloat16 l2 = __float2bfloat16_rn(v.z - __bfloat162float(h2));
    __nv_bfloat16 l3 = __float2bfloat16_rn(v.w - __bfloat162float(h3));
    hi.x = pack_bf2(h0, h1); hi.y = pack_bf2(h2, h3);
    lo.x = pack_bf2(l0, l1); lo.y = pack_bf2(l2, l3);
}

// ============================================================
// split-bf16 mma.sync GEMM (z-batched over two A/C pairs)
// limb-pass-reordered MMAs, single sync per K stage.
// ============================================================
#define LDH 40
#define ARR (128 * LDH)
#define STG (4 * ARR)
#define GEMM_SMEM (2 * STG * 2)

__global__ __launch_bounds__(256, 1) void gemm_mma(
    const float* __restrict__ A0, const float* __restrict__ A1,
    const float* __restrict__ B, const float* __restrict__ bias,
    float* __restrict__ C0, float* __restrict__ C1,
    int M, int N, int K)
{
    extern __shared__ __align__(16) __nv_bfloat16 sh[];
    const int tid  = threadIdx.x;
    const int wid  = tid >> 5;
    const int lane = tid & 31;
    const int m0 = blockIdx.y * 128, n0 = blockIdx.x * 128;
    const int wm = (wid >> 2) * 64;
    const int wn = (wid & 3) * 32;
    const int S  = K / 32;

    const float* A = blockIdx.z ? A1 : A0;
    float*       C = blockIdx.z ? C1 : C0;

    const uint32_t sbase = smem_u32(sh);
    const int a_row = (wm + (lane & 15)) * LDH + ((lane >> 4) << 3);
    const int b_row = (wn + ((lane >> 4) << 3) + (lane & 7)) * LDH + (((lane >> 3) & 1) << 3);

    float acc[4][4][4];
#pragma unroll
    for (int i = 0; i < 4; i++)
#pragma unroll
        for (int j = 0; j < 4; j++)
#pragma unroll
            for (int r = 0; r < 4; r++) acc[i][j][r] = 0.f;

    const int g_row = tid >> 3;
    const int g_kc  = (tid & 7) << 2;

    float4 pa[4], pb[4];
#pragma unroll
    for (int u = 0; u < 4; u++) {
        int row = g_row + u * 32;
        pa[u] = *(const float4*)(A + (size_t)(m0 + row) * K + g_kc);
        pb[u] = *(const float4*)(B + (size_t)(n0 + row) * K + g_kc);
    }
    {
        __nv_bfloat16* st = sh;
#pragma unroll
        for (int u = 0; u < 4; u++) {
            int row = g_row + u * 32;
            int off = row * LDH + g_kc;
            uint2 hi, lo;
            split4(pa[u], hi, lo);
            *(uint2*)(st + off)        = hi;
            *(uint2*)(st + ARR + off)  = lo;
            split4(pb[u], hi, lo);
            *(uint2*)(st + 2*ARR + off) = hi;
            *(uint2*)(st + 3*ARR + off) = lo;
        }
    }
    __syncthreads();

    for (int s = 0; s < S; s++) {
        const int cur = s & 1;
        if (s + 1 < S) {
            const int kb = (s + 1) * 32;
#pragma unroll
            for (int u = 0; u < 4; u++) {
                int row = g_row + u * 32;
                pa[u] = *(const float4*)(A + (size_t)(m0 + row) * K + kb + g_kc);
                pb[u] = *(const float4*)(B + (size_t)(n0 + row) * K + kb + g_kc);
            }
        }

        const uint32_t stg = sbase + (uint32_t)(cur * STG) * 2u;
#pragma unroll
        for (int ks = 0; ks < 2; ks++) {
            const int kofs = ks * 16;
            uint32_t ah[4][4], al[4][4];
#pragma unroll
            for (int mt = 0; mt < 4; mt++) {
                uint32_t ra = stg + (uint32_t)(a_row + mt * 16 * LDH + kofs) * 2u;
                ldsm_x4(ra,              ah[mt][0], ah[mt][1], ah[mt][2], ah[mt][3]);
                ldsm_x4(ra + ARR * 2u,   al[mt][0], al[mt][1], al[mt][2], al[mt][3]);
            }
            uint32_t bh[4][2], bl[4][2];
#pragma unroll
            for (int p = 0; p < 2; p++) {
                uint32_t rb = stg + (uint32_t)(b_row + p * 16 * LDH + kofs) * 2u + 2u * ARR * 2u;
                ldsm_x4(rb,             bh[p*2][0], bh[p*2][1], bh[p*2+1][0], bh[p*2+1][1]);
                ldsm_x4(rb + ARR * 2u,  bl[p*2][0], bl[p*2][1], bl[p*2+1][0], bl[p*2+1][1]);
            }
            // limb pass 1: Ah*Bh — 16 independent accumulators
#pragma unroll
            for (int mt = 0; mt < 4; mt++)
#pragma unroll
                for (int nt = 0; nt < 4; nt++)
                    mma_bf16(acc[mt][nt], ah[mt], bh[nt][0], bh[nt][1]);
            // limb pass 2: Ah*Bl
#pragma unroll
            for (int mt = 0; mt < 4; mt++)
#pragma unroll
                for (int nt = 0; nt < 4; nt++)
                    mma_bf16(acc[mt][nt], ah[mt], bl[nt][0], bl[nt][1]);
            // limb pass 3: Al*Bh
#pragma unroll
            for (int mt = 0; mt < 4; mt++)
#pragma unroll
                for (int nt = 0; nt < 4; nt++)
                    mma_bf16(acc[mt][nt], al[mt], bh[nt][0], bh[nt][1]);
        }

        if (s + 1 < S) {
            // safe: buffer nxt was last read in stage s-1, guarded by that sync
            __nv_bfloat16* st = sh + (size_t)((s + 1) & 1) * STG;
#pragma unroll
            for (int u = 0; u < 4; u++) {
                int row = g_row + u * 32;
                int off = row * LDH + g_kc;
                uint2 hi, lo;
                split4(pa[u], hi, lo);
                *(uint2*)(st + off)        = hi;
                *(uint2*)(st + ARR + off)  = lo;
                split4(pb[u], hi, lo);
                *(uint2*)(st + 2*ARR + off) = hi;
                *(uint2*)(st + 3*ARR + off) = lo;
            }
            __syncthreads();
        }
    }

#pragma unroll
    for (int mt = 0; mt < 4; mt++) {
        int row0 = m0 + wm + mt * 16 + (lane >> 2);
#pragma unroll
        for (int nt = 0; nt < 4; nt++) {
            int col = n0 + wn + nt * 8 + (lane & 3) * 2;
            float b0 = 0.f, b1 = 0.f;
            if (bias) { b0 = __ldg(bias + col); b1 = __ldg(bias + col + 1); }
            float2 v0 = make_float2(acc[mt][nt][0] + b0, acc[mt][nt][1] + b1);
            float2 v1 = make_float2(acc[mt][nt][2] + b0, acc[mt][nt][3] + b1);
            *(float2*)(C + (size_t)row0 * N + col)       = v0;
            *(float2*)(C + (size_t)(row0 + 8) * N + col) = v1;
        }
    }
}

// ============================================================
// Dual-softmax flash attention on mma.sync (split-bf16).
// Double-buffered K/V tiles, register prefetch, 1 sync/iter,
// stream-interleaved MMA issue.
// ============================================================
#define AQS 72                           // halves per row (64 + 8 pad)
#define OQ1H 0
#define OQ1L (128*AQS)
#define OQ2H (2*128*AQS)
#define OQ2L (3*128*AQS)
#define OKV  (4*128*AQS)                 // start of KV buffers (halves)
#define KVH  (4*64*AQS)                  // halves per KV buffer
#define ATT_SMEM ((OKV + 2*KVH) * 2)     // 147456 bytes

__global__ __launch_bounds__(256, 1) void attention_mma()
{
    extern __shared__ __align__(16) __nv_bfloat16 sh[];
    const uint32_t sb = smem_u32(sh);
    const int tid  = threadIdx.x;
    const int wid  = tid >> 5;
    const int lane = tid & 31;
    const int wm   = wid * 16;

    const int b    = blockIdx.z;
    const int h    = blockIdx.y >> 1;
    const int pair = blockIdx.y & 1;
    const int q0   = blockIdx.x * 128;

    const float* bx = g_qkv_x + (size_t)b * SEQ * QKV_DIM;
    const float* by = g_qkv_y + (size_t)b * SEQ * QKV_DIM;
    const int hoff  = h * HD;

    const float *Q1src, *Q2src, *Ksrc;
    float* outp;
    if (pair == 0) { Q1src = bx + C_DIM; Q2src = by;  Ksrc = bx + 2 * C_DIM; outp = g_att_x; }
    else           { Q1src = by + C_DIM; Q2src = bx;  Ksrc = by + 2 * C_DIM; outp = g_att_y; }
    const float* Vsrc = bx + 3 * C_DIM;   // vy = vx in the reference

    // per-thread load slots
    const int k_rowt = tid >> 4;           // +u*16? (below uses idx pattern)
    const int v_jp = tid & 31;
    const int v_d0 = (tid >> 5) * 8;

    // ---- load Q tiles as pre-scaled limbs ----
#pragma unroll
    for (int u = 0; u < 8; u++) {
        int idx = u * 256 + tid;
        int row = idx >> 4;
        int c4  = (idx & 15) << 2;
        float4 v1 = *(const float4*)(Q1src + (size_t)(q0 + row) * QKV_DIM + hoff + c4);
        float4 v2 = *(const float4*)(Q2src + (size_t)(q0 + row) * QKV_DIM + hoff + c4);
        v1.x *= 0.125f; v1.y *= 0.125f; v1.z *= 0.125f; v1.w *= 0.125f;
        v2.x *= -0.125f; v2.y *= -0.125f; v2.z *= -0.125f; v2.w *= -0.125f;
        uint2 hi, lo;
        int off = row * AQS + c4;
        split4(v1, hi, lo);
        *(uint2*)(sh + OQ1H + off) = hi;
        *(uint2*)(sh + OQ1L + off) = lo;
        split4(v2, hi, lo);
        *(uint2*)(sh + OQ2H + off) = hi;
        *(uint2*)(sh + OQ2L + off) = lo;
    }

    // ---- load KV tile 0 into buffer 0 ----
    {
#pragma unroll
        for (int u = 0; u < 4; u++) {
            int idx = u * 256 + tid;
            int row = idx >> 4;
            int c4  = (idx & 15) << 2;
            float4 kv = *(const float4*)(Ksrc + (size_t)row * QKV_DIM + hoff + c4);
            uint2 hi, lo;
            split4(kv, hi, lo);
            int off = row * AQS + c4;
            *(uint2*)(sh + OKV + off)            = hi;
            *(uint2*)(sh + OKV + 64*AQS + off)   = lo;
        }
        const float* v0p = Vsrc + (size_t)(2 * v_jp)     * QKV_DIM + hoff + v_d0;
        const float* v1p = Vsrc + (size_t)(2 * v_jp + 1) * QKV_DIM + hoff + v_d0;
        float4 va0 = *(const float4*)(v0p);
        float4 va1 = *(const float4*)(v0p + 4);
        float4 vb0 = *(const float4*)(v1p);
        float4 vb1 = *(const float4*)(v1p + 4);
        float f0[8] = {va0.x, va0.y, va0.z, va0.w, va1.x, va1.y, va1.z, va1.w};
        float f1[8] = {vb0.x, vb0.y, vb0.z, vb0.w, vb1.x, vb1.y, vb1.z, vb1.w};
#pragma unroll
        for (int i = 0; i < 8; i++) {
            __nv_bfloat16 h0 = __float2bfloat16_rn(f0[i]);
            __nv_bfloat16 h1 = __float2bfloat16_rn(f1[i]);
            __nv_bfloat16 e0 = __float2bfloat16_rn(f0[i] - __bfloat162float(h0));
            __nv_bfloat16 e1 = __float2bfloat16_rn(f1[i] - __bfloat162float(h1));
            *(uint32_t*)(sh + OKV + 2*64*AQS + (v_d0 + i) * AQS + 2 * v_jp) = pack_bf2(h0, h1);
            *(uint32_t*)(sh + OKV + 3*64*AQS + (v_d0 + i) * AQS + 2 * v_jp) = pack_bf2(e0, e1);
        }
    }
    __syncthreads();

    // accumulators / softmax state
    float o1[8][4], o2[8][4];
#pragma unroll
    for (int d = 0; d < 8; d++)
#pragma unroll
        for (int r = 0; r < 4; r++) { o1[d][r] = 0.f; o2[d][r] = 0.f; }
    float m1lo = -1e30f, m1hi = -1e30f, l1lo = 0.f, l1hi = 0.f;
    float m2lo = -1e30f, m2hi = -1e30f, l2lo = 0.f, l2hi = 0.f;

    const uint32_t a_base = (uint32_t)((wm + (lane & 15)) * AQS + ((lane >> 4) << 3)) * 2u;
    const uint32_t b_base = (uint32_t)((((lane >> 4) << 3) + (lane & 7)) * AQS
                                       + (((lane >> 3) & 1) << 3)) * 2u;

    for (int kt = 0; kt < 16; kt++) {
        const int cur = kt & 1;
        const uint32_t kvb = (uint32_t)(OKV + cur * KVH) * 2u;   // byte offset

        // ---- prefetch next KV tile into registers ----
        float4 kpre[4], vpre[4];
        if (kt < 15) {
            const int j0n = (kt + 1) * 64;
#pragma unroll
            for (int u = 0; u < 4; u++) {
                int idx = u * 256 + tid;
                int row = idx >> 4;
                int c4  = (idx & 15) << 2;
                kpre[u] = *(const float4*)(Ksrc + (size_t)(j0n + row) * QKV_DIM + hoff + c4);
            }
            const float* v0p = Vsrc + (size_t)(j0n + 2 * v_jp)     * QKV_DIM + hoff + v_d0;
            const float* v1p = Vsrc + (size_t)(j0n + 2 * v_jp + 1) * QKV_DIM + hoff + v_d0;
            vpre[0] = *(const float4*)(v0p);
            vpre[1] = *(const float4*)(v0p + 4);
            vpre[2] = *(const float4*)(v1p);
            vpre[3] = *(const float4*)(v1p + 4);
        }

        // ---- S = Q K^T (both streams, 3 limbs, stream-interleaved) ----
        float s1[8][4], s2[8][4];
#pragma unroll
        for (int n = 0; n < 8; n++)
#pragma unroll
            for (int r = 0; r < 4; r++) { s1[n][r] = 0.f; s2[n][r] = 0.f; }

#pragma unroll
        for (int ks = 0; ks < 4; ks++) {
            const uint32_t kofs = (uint32_t)(ks * 16) * 2u;
            uint32_t a1h[4], a1l[4], a2h[4], a2l[4];
            ldsm_x4(sb + OQ1H*2u + a_base + kofs, a1h[0], a1h[1], a1h[2], a1h[3]);
            ldsm_x4(sb + OQ1L*2u + a_base + kofs, a1l[0], a1l[1], a1l[2], a1l[3]);
            ldsm_x4(sb + OQ2H*2u + a_base + kofs, a2h[0], a2h[1], a2h[2], a2h[3]);
            ldsm_x4(sb + OQ2L*2u + a_base + kofs, a2l[0], a2l[1], a2l[2], a2l[3]);
#pragma unroll
            for (int jt = 0; jt < 4; jt++) {
                uint32_t rb = sb + kvb + b_base + (uint32_t)(jt * 16 * AQS) * 2u + kofs;
                uint32_t bh[2][2], bl[2][2];
                ldsm_x4(rb,                         bh[0][0], bh[0][1], bh[1][0], bh[1][1]);
                ldsm_x4(rb + (uint32_t)(64*AQS)*2u, bl[0][0], bl[0][1], bl[1][0], bl[1][1]);
#pragma unroll
                for (int q = 0; q < 2; q++) {
                    int nt = jt * 2 + q;
                    // interleave streams: same-acc reuse distance 2
                    mma_bf16(s1[nt], a1h, bh[q][0], bh[q][1]);
                    mma_bf16(s2[nt], a2h, bh[q][0], bh[q][1]);
                    mma_bf16(s1[nt], a1h, bl[q][0], bl[q][1]);
                    mma_bf16(s2[nt], a2h, bl[q][0], bl[q][1]);
                    mma_bf16(s1[nt], a1l, bh[q][0], bh[q][1]);
                    mma_bf16(s2[nt], a2l, bh[q][0], bh[q][1]);
                }
            }
        }

        // ---- store prefetched tile into the other buffer ----
        if (kt < 15) {
            const int nb = OKV + (cur ^ 1) * KVH;
#pragma unroll
            for (int u = 0; u < 4; u++) {
                int idx = u * 256 + tid;
                int row = idx >> 4;
                int c4  = (idx & 15) << 2;
                uint2 hi, lo;
                split4(kpre[u], hi, lo);
                int off = row * AQS + c4;
                *(uint2*)(sh + nb + off)          = hi;
                *(uint2*)(sh + nb + 64*AQS + off) = lo;
            }
            float f0[8] = {vpre[0].x, vpre[0].y, vpre[0].z, vpre[0].w,
                           vpre[1].x, vpre[1].y, vpre[1].z, vpre[1].w};
            float f1[8] = {vpre[2].x, vpre[2].y, vpre[2].z, vpre[2].w,
                           vpre[3].x, vpre[3].y, vpre[3].z, vpre[3].w};
#pragma unroll
            for (int i = 0; i < 8; i++) {
                __nv_bfloat16 h0 = __float2bfloat16_rn(f0[i]);
                __nv_bfloat16 h1 = __float2bfloat16_rn(f1[i]);
                __nv_bfloat16 e0 = __float2bfloat16_rn(f0[i] - __bfloat162float(h0));
                __nv_bfloat16 e1 = __float2bfloat16_rn(f1[i] - __bfloat162float(h1));
                *(uint32_t*)(sh + nb + 2*64*AQS + (v_d0 + i) * AQS + 2 * v_jp) = pack_bf2(h0, h1);
                *(uint32_t*)(sh + nb + 3*64*AQS + (v_d0 + i) * AQS + 2 * v_jp) = pack_bf2(e0, e1);
            }
        }

        // ---- online softmax (per stream), produce P limb A-fragments ----
        uint32_t p1h[8][2], p1l[8][2], p2h[8][2], p2l[8][2];
        {
            float mxlo = -1e30f, mxhi = -1e30f;
#pragma unroll
            for (int n = 0; n < 8; n++) {
                mxlo = fmaxf(mxlo, fmaxf(s1[n][0], s1[n][1]));
                mxhi = fmaxf(mxhi, fmaxf(s1[n][2], s1[n][3]));
            }
            mxlo = fmaxf(mxlo, __shfl_xor_sync(0xffffffffu, mxlo, 1));
            mxlo = fmaxf(mxlo, __shfl_xor_sync(0xffffffffu, mxlo, 2));
            mxhi = fmaxf(mxhi, __shfl_xor_sync(0xffffffffu, mxhi, 1));
            mxhi = fmaxf(mxhi, __shfl_xor_sync(0xffffffffu, mxhi, 2));
            float mnlo = fmaxf(m1lo, mxlo), mnhi = fmaxf(m1hi, mxhi);
            float clo = __expf(m1lo - mnlo), chi = __expf(m1hi - mnhi);
            m1lo = mnlo; m1hi = mnhi;
            float sl = 0.f, shh = 0.f;
#pragma unroll
            for (int n = 0; n < 8; n++) {
                float p0 = __expf(s1[n][0] - mnlo);
                float p1 = __expf(s1[n][1] - mnlo);
                float p2 = __expf(s1[n][2] - mnhi);
                float p3 = __expf(s1[n][3] - mnhi);
                sl += p0 + p1; shh += p2 + p3;
                __nv_bfloat16 h0 = __float2bfloat16_rn(p0), h1 = __float2bfloat16_rn(p1);
                __nv_bfloat16 h2 = __float2bfloat16_rn(p2), h3 = __float2bfloat16_rn(p3);
                p1h[n][0] = pack_bf2(h0, h1);
                p1h[n][1] = pack_bf2(h2, h3);
                p1l[n][0] = pack_bf2(__float2bfloat16_rn(p0 - __bfloat162float(h0)),
                                     __float2bfloat16_rn(p1 - __bfloat162float(h1)));
                p1l[n][1] = pack_bf2(__float2bfloat16_rn(p2 - __bfloat162float(h2)),
                                     __float2bfloat16_rn(p3 - __bfloat162float(h3)));
            }
            sl  += __shfl_xor_sync(0xffffffffu, sl, 1);
            sl  += __shfl_xor_sync(0xffffffffu, sl, 2);
            shh += __shfl_xor_sync(0xffffffffu, shh, 1);
            shh += __shfl_xor_sync(0xffffffffu, shh, 2);
            l1lo = l1lo * clo + sl; l1hi = l1hi * chi + shh;
#pragma unroll
            for (int d = 0; d < 8; d++) {
                o1[d][0] *= clo; o1[d][1] *= clo;
                o1[d][2] *= chi; o1[d][3] *= chi;
            }
        }
        {
            float mxlo = -1e30f, mxhi = -1e30f;
#pragma unroll
            for (int n = 0; n < 8; n++) {
                mxlo = fmaxf(mxlo, fmaxf(s2[n][0], s2[n][1]));
                mxhi = fmaxf(mxhi, fmaxf(s2[n][2], s2[n][3]));
            }
            mxlo = fmaxf(mxlo, __shfl_xor_sync(0xffffffffu, mxlo, 1));
            mxlo = fmaxf(mxlo, __shfl_xor_sync(0xffffffffu, mxlo, 2));
            mxhi = fmaxf(mxhi, __shfl_xor_sync(0xffffffffu, mxhi, 1));
            mxhi = fmaxf(mxhi, __shfl_xor_sync(0xffffffffu, mxhi, 2));
            float mnlo = fmaxf(m2lo, mxlo), mnhi = fmaxf(m2hi, mxhi);
            float clo = __expf(m2lo - mnlo), chi = __expf(m2hi - mnhi);
            m2lo = mnlo; m2hi = mnhi;
            float sl = 0.f, shh = 0.f;
#pragma unroll
            for (int n = 0; n < 8; n++) {
                float p0 = __expf(s2[n][0] - mnlo);
                float p1 = __expf(s2[n][1] - mnlo);
                float p2 = __expf(s2[n][2] - mnhi);
                float p3 = __expf(s2[n][3] - mnhi);
                sl += p0 + p1; shh += p2 + p3;
                __nv_bfloat16 h0 = __float2bfloat16_rn(p0), h1 = __float2bfloat16_rn(p1);
                __nv_bfloat16 h2 = __float2bfloat16_rn(p2), h3 = __float2bfloat16_rn(p3);
                p2h[n][0] = pack_bf2(h0, h1);
                p2h[n][1] = pack_bf2(h2, h3);
                p2l[n][0] = pack_bf2(__float2bfloat16_rn(p0 - __bfloat162float(h0)),
                                     __float2bfloat16_rn(p1 - __bfloat162float(h1)));
                p2l[n][1] = pack_bf2(__float2bfloat16_rn(p2 - __bfloat162float(h2)),
                                     __float2bfloat16_rn(p3 - __bfloat162float(h3)));
            }
            sl  += __shfl_xor_sync(0xffffffffu, sl, 1);
            sl  += __shfl_xor_sync(0xffffffffu, sl, 2);
            shh += __shfl_xor_sync(0xffffffffu, shh, 1);
            shh += __shfl_xor_sync(0xffffffffu, shh, 2);
            l2lo = l2lo * clo + sl; l2hi = l2hi * chi + shh;
#pragma unroll
            for (int d = 0; d < 8; d++) {
                o2[d][0] *= clo; o2[d][1] *= clo;
                o2[d][2] *= chi; o2[d][3] *= chi;
            }
        }

        // ---- O += P V (stream-interleaved limb MMAs) ----
        const uint32_t vbase = kvb + (uint32_t)(2 * 64 * AQS) * 2u;
#pragma unroll
        for (int ks = 0; ks < 4; ks++) {
            uint32_t a1hf[4] = { p1h[2*ks][0], p1h[2*ks][1], p1h[2*ks+1][0], p1h[2*ks+1][1] };
            uint32_t a1lf[4] = { p1l[2*ks][0], p1l[2*ks][1], p1l[2*ks+1][0], p1l[2*ks+1][1] };
            uint32_t a2hf[4] = { p2h[2*ks][0], p2h[2*ks][1], p2h[2*ks+1][0], p2h[2*ks+1][1] };
            uint32_t a2lf[4] = { p2l[2*ks][0], p2l[2*ks][1], p2l[2*ks+1][0], p2l[2*ks+1][1] };
            const uint32_t kofs = (uint32_t)(ks * 16) * 2u;
#pragma unroll
            for (int dt2 = 0; dt2 < 4; dt2++) {
                uint32_t rb = sb + vbase + b_base + (uint32_t)(dt2 * 16 * AQS) * 2u + kofs;
                uint32_t vh[2][2], vl[2][2];
                ldsm_x4(rb,                         vh[0][0], vh[0][1], vh[1][0], vh[1][1]);
                ldsm_x4(rb + (uint32_t)(64*AQS)*2u, vl[0][0], vl[0][1], vl[1][0], vl[1][1]);
#pragma unroll
                for (int q = 0; q < 2; q++) {
                    int dt = dt2 * 2 + q;
                    mma_bf16(o1[dt], a1hf, vh[q][0], vh[q][1]);
                    mma_bf16(o2[dt], a2hf, vh[q][0], vh[q][1]);
                    mma_bf16(o1[dt], a1hf, vl[q][0], vl[q][1]);
                    mma_bf16(o2[dt], a2hf, vl[q][0], vl[q][1]);
                    mma_bf16(o1[dt], a1lf, vh[q][0], vh[q][1]);
                    mma_bf16(o2[dt], a2lf, vh[q][0], vh[q][1]);
                }
            }
        }

        if (kt < 15) __syncthreads();
    }

    // ---- epilogue: out = O1/l1 + O2/l2 ----
    const float i1lo = 1.f / l1lo, i1hi = 1.f / l1hi;
    const float i2lo = 1.f / l2lo, i2hi = 1.f / l2hi;
    float* obase = outp + (size_t)b * SEQ * C_DIM;
    const int r0 = q0 + wm + (lane >> 2);
    const int cb = hoff + (lane & 3) * 2;
#pragma unroll
    for (int dt = 0; dt < 8; dt++) {
        int col = cb + dt * 8;
        float2 vlo = make_float2(o1[dt][0] * i1lo + o2[dt][0] * i2lo,
                                 o1[dt][1] * i1lo + o2[dt][1] * i2lo);
        float2 vhi = make_float2(o1[dt][2] * i1hi + o2[dt][2] * i2hi,
                                 o1[dt][3] * i1hi + o2[dt][3] * i2hi);
        *(float2*)(obase + (size_t)r0 * C_DIM + col)       = vlo;
        *(float2*)(obase + (size_t)(r0 + 8) * C_DIM + col) = vhi;
    }
    (void)k_rowt;
}

// ============================================================
extern "C" void kernel_launch(void* const* d_in, const int* in_sizes, int n_in,
                              void* d_out, int out_size)
{
    const float* x      = (const float*)d_in[0];
    const float* y      = (const float*)d_in[1];
    const float* w_qkv  = (const float*)d_in[2];
    const float* w_proj = (const float*)d_in[3];
    const float* b_proj = (const float*)d_in[4];
    float* out = (float*)d_out;

    float *qx, *qy, *ax, *ay;
    cudaGetSymbolAddress((void**)&qx, g_qkv_x);
    cudaGetSymbolAddress((void**)&qy, g_qkv_y);
    cudaGetSymbolAddress((void**)&ax, g_att_x);
    cudaGetSymbolAddress((void**)&ay, g_att_y);

    cudaFuncSetAttribute(gemm_mma,
                         cudaFuncAttributeMaxDynamicSharedMemorySize, GEMM_SMEM);
    cudaFuncSetAttribute(attention_mma,
                         cudaFuncAttributeMaxDynamicSharedMemorySize, ATT_SMEM);

    // 1) QKV projections, x and y batched in z
    dim3 g1(QKV_DIM / 128, M_ROWS / 128, 2);
    gemm_mma<<<g1, 256, GEMM_SMEM>>>(x, y, w_qkv, nullptr, qx, qy,
                                     M_ROWS, QKV_DIM, C_DIM);

    // 2) fused dual-softmax attention (mma.sync)
    attention_mma<<<dim3(SEQ / 128, HEADS * 2, BATCH), 256, ATT_SMEM>>>();

    // 3) output projections + bias, both branches batched in z
    dim3 g2(C_DIM / 128, M_ROWS / 128, 2);
    gemm_mma<<<g2, 256, GEMM_SMEM>>>(ax, ay, w_proj, b_proj,
                                     out, out + (size_t)M_ROWS * C_DIM,
                                     M_ROWS, C_DIM, C_DIM);
}